// round 1
// baseline (speedup 1.0000x reference)
#include <cuda_runtime.h>
#include <math.h>

// Problem constants
#define DIMC   64
#define MULTI  4
#define NPIX   (8*256*256)        // 524288 pixels
#define PT     64                 // pixels per tile
#define NTILES (NPIX/PT)          // 8192
#define NTHREADS 256
#define NBLOCKS  148              // persistent, 1 block/SM on B200

// smem layout (floats):
//   wgT[4][64][64]   : 16384 floats (wg transposed to [m][i][o], o contiguous)
//   ys [4][64][68]   : 17408 floats (y tile [m][i][p], p padded 64->68 for banks)
#define WG_FLOATS 16384
#define YP        68
#define YS_FLOATS (4*64*YP)
#define SMEM_BYTES ((WG_FLOATS + YS_FLOATS)*4)

__device__ __forceinline__ float gelu_exact(float v) {
    // exact erf-based GELU, matches jax.nn.gelu(approximate=False)
    return 0.5f * v * (1.0f + erff(v * 0.70710678118654752f));
}

__global__ void __launch_bounds__(NTHREADS, 1)
mpmlp_kernel(const float* __restrict__ x,
             const float* __restrict__ w1,
             const float* __restrict__ wg,
             const float* __restrict__ w2,
             float* __restrict__ out)
{
    extern __shared__ float sm[];
    float* wgT = sm;                 // [m][i][o]
    float* ys  = sm + WG_FLOATS;     // [m][i][p(68)]

    const int tid = threadIdx.x;

    // ---- one-time: load wg with transpose (m,o,i) -> (m,i,o) ----
    for (int idx = tid; idx < WG_FLOATS; idx += NTHREADS) {
        int m = idx >> 12;
        int o = (idx >> 6) & 63;
        int i = idx & 63;
        wgT[(m*64 + i)*64 + o] = wg[idx];
    }

    // ---- GEMM-side thread mapping ----
    // 256 threads: og = tid&31 (column groups), pg = tid>>5 (pixel groups)
    // colA = 4*og in [0,128)  -> mA in {0,1}, oA = colA & 63
    // colB = colA + 128       -> mB = mA + 2, same oA
    const int og = tid & 31;
    const int pg = tid >> 5;           // 0..7
    const int p0 = pg * 8;             // 8-pixel micro tile
    const int colA = og * 4;
    const int mA = colA >> 6;          // 0 or 1
    const int oA = colA & 63;
    const int mB = mA + 2;

    // ---- producer-side thread mapping ----
    const int pi = tid & 63;           // channel i owned by this thread
    const int pq = tid >> 6;           // 0..3

    // preload small weights into registers
    const float4 w1v = *reinterpret_cast<const float4*>(w1 + pi*4); // w1[pi][0..3]
    float w2A[4], w2B[4];
#pragma unroll
    for (int t = 0; t < 4; t++) {
        w2A[t] = w2[(oA + t)*4 + mA];
        w2B[t] = w2[(oA + t)*4 + mB];
    }

    __syncthreads();

    for (int tile = blockIdx.x; tile < NTILES; tile += gridDim.x) {
        const long base = (long)tile * PT * DIMC;

        // ================= producer: y = gelu(x * w1) into smem =================
        // thread owns channel pi; covers 16 pixels in 4 groups of 4 (float4 STS over p)
#pragma unroll
        for (int r = 0; r < 4; r++) {
            const int pp = r*16 + pq*4;
            float xv[4];
#pragma unroll
            for (int t = 0; t < 4; t++)
                xv[t] = x[base + (long)(pp + t)*DIMC + pi];
            const float w1a[4] = {w1v.x, w1v.y, w1v.z, w1v.w};
#pragma unroll
            for (int m = 0; m < 4; m++) {
                float4 yv;
                yv.x = gelu_exact(xv[0]*w1a[m]);
                yv.y = gelu_exact(xv[1]*w1a[m]);
                yv.z = gelu_exact(xv[2]*w1a[m]);
                yv.w = gelu_exact(xv[3]*w1a[m]);
                *reinterpret_cast<float4*>(&ys[(m*64 + pi)*YP + pp]) = yv;
            }
        }
        __syncthreads();

        // ================= middle GEMM: z_pre = Y @ WgT, 8p x (4+4) cols =================
        float accA[8][4];
        float accB[8][4];
#pragma unroll
        for (int p = 0; p < 8; p++)
#pragma unroll
            for (int t = 0; t < 4; t++) { accA[p][t] = 0.0f; accB[p][t] = 0.0f; }

        const float* wgA = &wgT[(mA*64)*64 + oA];
        const float* wgB = &wgT[(mB*64)*64 + oA];
        const float* ysA = &ys[(mA*64)*YP + p0];
        const float* ysB = &ys[(mB*64)*YP + p0];

#pragma unroll 8
        for (int k = 0; k < 64; k++) {
            const float4 wa  = *reinterpret_cast<const float4*>(wgA + k*64);
            const float4 wb  = *reinterpret_cast<const float4*>(wgB + k*64);
            const float4 ya0 = *reinterpret_cast<const float4*>(ysA + k*YP);
            const float4 ya1 = *reinterpret_cast<const float4*>(ysA + k*YP + 4);
            const float4 yb0 = *reinterpret_cast<const float4*>(ysB + k*YP);
            const float4 yb1 = *reinterpret_cast<const float4*>(ysB + k*YP + 4);

            const float yav[8] = {ya0.x, ya0.y, ya0.z, ya0.w, ya1.x, ya1.y, ya1.z, ya1.w};
            const float ybv[8] = {yb0.x, yb0.y, yb0.z, yb0.w, yb1.x, yb1.y, yb1.z, yb1.w};
            const float wav[4] = {wa.x, wa.y, wa.z, wa.w};
            const float wbv[4] = {wb.x, wb.y, wb.z, wb.w};

#pragma unroll
            for (int p = 0; p < 8; p++) {
#pragma unroll
                for (int t = 0; t < 4; t++) {
                    accA[p][t] = fmaf(yav[p], wav[t], accA[p][t]);
                    accB[p][t] = fmaf(ybv[p], wbv[t], accB[p][t]);
                }
            }
        }
        __syncthreads();   // all reads of ys done before next tile's producer

        // ================= epilogue: gelu(z), contract over m, store =================
        // lane og holds m = {mA, mB} = {0,2} or {1,3}; partner lane og^16 holds the
        // complementary pair for the SAME output channels oA..oA+3.
#pragma unroll
        for (int p = 0; p < 8; p++) {
            float part[4];
#pragma unroll
            for (int t = 0; t < 4; t++) {
                part[t] = gelu_exact(accA[p][t]) * w2A[t]
                        + gelu_exact(accB[p][t]) * w2B[t];
            }
            float other[4];
#pragma unroll
            for (int t = 0; t < 4; t++)
                other[t] = __shfl_xor_sync(0xffffffffu, part[t], 16);

            if (og < 16) {
                float4 o4;
                o4.x = part[0] + other[0];
                o4.y = part[1] + other[1];
                o4.z = part[2] + other[2];
                o4.w = part[3] + other[3];
                *reinterpret_cast<float4*>(&out[base + (long)(p0 + p)*DIMC + oA]) = o4;
            }
        }
    }
}

extern "C" void kernel_launch(void* const* d_in, const int* in_sizes, int n_in,
                              void* d_out, int out_size)
{
    const float* x  = (const float*)d_in[0];
    const float* w1 = (const float*)d_in[1];
    const float* wg = (const float*)d_in[2];
    const float* w2 = (const float*)d_in[3];
    float* out = (float*)d_out;

    cudaFuncSetAttribute(mpmlp_kernel,
                         cudaFuncAttributeMaxDynamicSharedMemorySize, SMEM_BYTES);
    mpmlp_kernel<<<NBLOCKS, NTHREADS, SMEM_BYTES>>>(x, w1, wg, w2, out);
}

// round 2
// speedup vs baseline: 1.0861x; 1.0861x over previous
#include <cuda_runtime.h>
#include <math.h>

// Problem constants
#define DIMC   64
#define MULTI  4
#define NPIX   (8*256*256)        // 524288 pixels
#define PT     64                 // pixels per tile
#define NTILES (NPIX/PT)          // 8192
#define NTHREADS 256
#define NBLOCKS  148              // persistent, 1 block/SM

// smem layout (floats):
//   wgT[4][64][64]   : 16384 floats (wg transposed to [m][i][o], o contiguous)
//   ys [4][64][68]   : 17408 floats (y tile [m][i][p], p padded 64->68: stride
//                      68 words == 4 mod 32 -> conflict-free 128-bit phases)
#define WG_FLOATS 16384
#define YP        68
#define YS_FLOATS (4*64*YP)
#define SMEM_BYTES ((WG_FLOATS + YS_FLOATS)*4)

typedef unsigned long long ull;

__device__ __forceinline__ float gelu_exact(float v) {
    // exact erf-based GELU, matches jax.nn.gelu(approximate=False)
    return 0.5f * v * (1.0f + erff(v * 0.70710678118654752f));
}

// packed fp32x2 FMA: d = a*b + d (elementwise on the two packed floats)
__device__ __forceinline__ void fma2(ull& d, ull a, ull b) {
    asm("fma.rn.f32x2 %0, %1, %2, %0;" : "+l"(d) : "l"(a), "l"(b));
}
// duplicate a scalar float into both halves of a b64 pair
__device__ __forceinline__ ull pack2(float v) {
    ull r;
    unsigned int u = __float_as_uint(v);
    asm("mov.b64 %0, {%1, %1};" : "=l"(r) : "r"(u));
    return r;
}
__device__ __forceinline__ float2 unpack2(ull v) {
    unsigned int lo, hi;
    asm("mov.b64 {%0, %1}, %2;" : "=r"(lo), "=r"(hi) : "l"(v));
    return make_float2(__uint_as_float(lo), __uint_as_float(hi));
}

__global__ void __launch_bounds__(NTHREADS, 1)
mpmlp_kernel(const float* __restrict__ x,
             const float* __restrict__ w1,
             const float* __restrict__ wg,
             const float* __restrict__ w2,
             float* __restrict__ out)
{
    extern __shared__ float sm[];
    float* wgT = sm;                 // [m][i][o]
    float* ys  = sm + WG_FLOATS;     // [m][i][p(68)]

    const int tid = threadIdx.x;

    // ---- one-time: load wg with transpose (m,o,i) -> (m,i,o) ----
    for (int idx = tid; idx < WG_FLOATS; idx += NTHREADS) {
        int m = idx >> 12;
        int o = (idx >> 6) & 63;
        int i = idx & 63;
        wgT[(m*64 + i)*64 + o] = wg[idx];
    }

    // ---- GEMM-side thread mapping ----
    // og = lane (column group), pg = warp (pixel group)
    // colA = 4*og in [0,128)  -> mA in {0,1}, oA = colA & 63
    // colB = colA + 128       -> mB = mA + 2, same oA
    const int og = tid & 31;
    const int pg = tid >> 5;           // 0..7
    const int p0 = pg * 8;             // 8-pixel micro tile
    const int colA = og * 4;
    const int mA = colA >> 6;          // 0 or 1
    const int oA = colA & 63;
    const int mB = mA + 2;

    // ---- producer-side thread mapping ----
    const int pi = tid & 63;           // channel i owned by this thread
    const int pq = tid >> 6;           // 0..3

    // preload small weights into registers
    const float4 w1v = *reinterpret_cast<const float4*>(w1 + pi*4); // w1[pi][0..3]
    float w2A[4], w2B[4];
#pragma unroll
    for (int t = 0; t < 4; t++) {
        w2A[t] = w2[(oA + t)*4 + mA];
        w2B[t] = w2[(oA + t)*4 + mB];
    }

    __syncthreads();

    for (int tile = blockIdx.x; tile < NTILES; tile += gridDim.x) {
        const long base = (long)tile * PT * DIMC;

        // ================= producer: y = gelu(x * w1) into smem =================
        // thread owns channel pi; covers 16 pixels in 4 groups of 4 (float4 STS over p)
#pragma unroll
        for (int r = 0; r < 4; r++) {
            const int pp = r*16 + pq*4;
            float xv[4];
#pragma unroll
            for (int t = 0; t < 4; t++)
                xv[t] = x[base + (long)(pp + t)*DIMC + pi];
            const float w1a[4] = {w1v.x, w1v.y, w1v.z, w1v.w};
#pragma unroll
            for (int m = 0; m < 4; m++) {
                float4 yv;
                yv.x = gelu_exact(xv[0]*w1a[m]);
                yv.y = gelu_exact(xv[1]*w1a[m]);
                yv.z = gelu_exact(xv[2]*w1a[m]);
                yv.w = gelu_exact(xv[3]*w1a[m]);
                *reinterpret_cast<float4*>(&ys[(m*64 + pi)*YP + pp]) = yv;
            }
        }
        __syncthreads();

        // ================= middle GEMM: z_pre = Y @ WgT =================
        // packed fp32x2 along the pixel dim: acc[pp][t] holds pixels
        // (p0+2pp, p0+2pp+1) for column oA+t. Two halves: mA and mB.
        ull accA2[4][4];
        ull accB2[4][4];
#pragma unroll
        for (int p = 0; p < 4; p++)
#pragma unroll
            for (int t = 0; t < 4; t++) { accA2[p][t] = 0ull; accB2[p][t] = 0ull; }

        const float* wgA = &wgT[(mA*64)*64 + oA];
        const float* wgB = &wgT[(mB*64)*64 + oA];
        const float* ysA = &ys[(mA*64)*YP + p0];
        const float* ysB = &ys[(mB*64)*YP + p0];

#pragma unroll 16
        for (int k = 0; k < 64; k++) {
            const float4 wa = *reinterpret_cast<const float4*>(wgA + k*64);
            const float4 wb = *reinterpret_cast<const float4*>(wgB + k*64);
            // y loads: warp-broadcast (all lanes in a warp share p0 within each m-half)
            const ulonglong2 ya01 = *reinterpret_cast<const ulonglong2*>(ysA + k*YP);
            const ulonglong2 ya23 = *reinterpret_cast<const ulonglong2*>(ysA + k*YP + 4);
            const ulonglong2 yb01 = *reinterpret_cast<const ulonglong2*>(ysB + k*YP);
            const ulonglong2 yb23 = *reinterpret_cast<const ulonglong2*>(ysB + k*YP + 4);

            const ull yav[4] = {ya01.x, ya01.y, ya23.x, ya23.y};
            const ull ybv[4] = {yb01.x, yb01.y, yb23.x, yb23.y};
            const ull wa2[4] = {pack2(wa.x), pack2(wa.y), pack2(wa.z), pack2(wa.w)};
            const ull wb2[4] = {pack2(wb.x), pack2(wb.y), pack2(wb.z), pack2(wb.w)};

#pragma unroll
            for (int p = 0; p < 4; p++) {
#pragma unroll
                for (int t = 0; t < 4; t++) {
                    fma2(accA2[p][t], yav[p], wa2[t]);
                    fma2(accB2[p][t], ybv[p], wb2[t]);
                }
            }
        }
        __syncthreads();   // all reads of ys done before next tile's producer

        // ================= epilogue: gelu(z), contract over m, store =================
        // lane og holds m = {mA, mB}; partner lane og^16 holds the complementary
        // m-pair for the SAME output channels oA..oA+3.
#pragma unroll
        for (int pp = 0; pp < 4; pp++) {
            float2 aA[4], aB[4];
#pragma unroll
            for (int t = 0; t < 4; t++) {
                aA[t] = unpack2(accA2[pp][t]);
                aB[t] = unpack2(accB2[pp][t]);
            }
#pragma unroll
            for (int h = 0; h < 2; h++) {
                const int p = 2*pp + h;
                float part[4];
#pragma unroll
                for (int t = 0; t < 4; t++) {
                    const float va = h ? aA[t].y : aA[t].x;
                    const float vb = h ? aB[t].y : aB[t].x;
                    part[t] = gelu_exact(va) * w2A[t] + gelu_exact(vb) * w2B[t];
                }
                float other[4];
#pragma unroll
                for (int t = 0; t < 4; t++)
                    other[t] = __shfl_xor_sync(0xffffffffu, part[t], 16);

                if (og < 16) {
                    float4 o4;
                    o4.x = part[0] + other[0];
                    o4.y = part[1] + other[1];
                    o4.z = part[2] + other[2];
                    o4.w = part[3] + other[3];
                    *reinterpret_cast<float4*>(&out[base + (long)(p0 + p)*DIMC + oA]) = o4;
                }
            }
        }
    }
}

extern "C" void kernel_launch(void* const* d_in, const int* in_sizes, int n_in,
                              void* d_out, int out_size)
{
    const float* x  = (const float*)d_in[0];
    const float* w1 = (const float*)d_in[1];
    const float* wg = (const float*)d_in[2];
    const float* w2 = (const float*)d_in[3];
    float* out = (float*)d_out;

    cudaFuncSetAttribute(mpmlp_kernel,
                         cudaFuncAttributeMaxDynamicSharedMemorySize, SMEM_BYTES);
    mpmlp_kernel<<<NBLOCKS, NTHREADS, SMEM_BYTES>>>(x, w1, wg, w2, out);
}